// round 4
// baseline (speedup 1.0000x reference)
#include <cuda_runtime.h>
#include <math.h>
#include <stdint.h>

#define BB   64
#define LL   1024
#define EE   80
#define HH   512
#define DEE  512
#define VV   500
#define KXX  (EE + HH)     // 592
#define FH   (4 * HH)      // 2048

// ---------------- scratch (no allocations allowed) ----------------
__device__ float  g_h[BB * HH];
__device__ float  g_u[BB * HH];
__device__ float  g_alpha[BB * LL];
__device__ float  g_ctx[BB * DEE];
__device__ float  g_newo[BB * 512];
__device__ float2 g_W1e2[512 * 512];   // (hi, lo) tf32 split of W1e, 2MB

// Fast tanh: 2 MUFU ops, abs err ~1e-6. Saturates correctly at +/-inf.
__device__ __forceinline__ float fast_tanh(float x) {
    return 1.0f - __fdividef(2.0f, __expf(2.0f * x) + 1.0f);
}
__device__ __forceinline__ float sigm(float x) {
    return 1.0f / (1.0f + expf(-x));
}

// Split fp32 into (hi, lo) tf32 pair: x ~= hi + lo with ~2^-22 residual.
__device__ __forceinline__ float2 split_tf32(float x) {
    uint32_t hb, lb;
    asm("cvt.rna.tf32.f32 %0, %1;" : "=r"(hb) : "f"(x));
    float hi = __uint_as_float(hb);
    float lo = x - hi;
    asm("cvt.rna.tf32.f32 %0, %1;" : "=r"(lb) : "f"(lo));
    return make_float2(hi, __uint_as_float(lb));
}

// m16n8k8 tf32 mma, fp32 accumulate
__device__ __forceinline__ void mma_tf32(float* c,
                                         uint32_t a0, uint32_t a1,
                                         uint32_t a2, uint32_t a3,
                                         uint32_t b0, uint32_t b1) {
    asm volatile(
        "mma.sync.aligned.m16n8k8.row.col.f32.tf32.tf32.f32 "
        "{%0,%1,%2,%3}, {%4,%5,%6,%7}, {%8,%9}, {%0,%1,%2,%3};\n"
        : "+f"(c[0]), "+f"(c[1]), "+f"(c[2]), "+f"(c[3])
        : "r"(a0), "r"(a1), "r"(a2), "r"(a3), "r"(b0), "r"(b1));
}

// =====================================================================
// Kernel 0: precompute tf32 hi/lo split of W1e (512x512)
// =====================================================================
__global__ void split_w1e_kernel(const float* __restrict__ W1e)
{
    int i = blockIdx.x * 256 + threadIdx.x;   // grid 1024 x 256 = 262144
    g_W1e2[i] = split_tf32(W1e[i]);
}

// =====================================================================
// Kernel 1: LSTM cell.  z = [inputs,o_prev]@Wk + h_prev@Uk + b ; gates.
// grid (4 j-tiles, 32 b-tiles), block 128.  BT=2 batches per block.
// =====================================================================
__global__ void lstm_kernel(const float* __restrict__ inputs,
                            const float* __restrict__ o_prev,
                            const float* __restrict__ h_prev,
                            const float* __restrict__ c_prev,
                            const float* __restrict__ Wk,
                            const float* __restrict__ Uk,
                            const float* __restrict__ bias,
                            float* __restrict__ out_h,
                            float* __restrict__ out_c)
{
    const int BT = 2;
    __shared__ float xs[BT][KXX];
    __shared__ float hs[BT][HH];
    const int tid = threadIdx.x;
    const int jg  = blockIdx.x * 128 + tid;    // gate column 0..511
    const int b0  = blockIdx.y * BT;

    for (int idx = tid; idx < BT * KXX; idx += 128) {
        int bb = idx / KXX, k = idx % KXX;
        xs[bb][k] = (k < EE) ? inputs[(b0 + bb) * EE + k]
                             : o_prev[(b0 + bb) * HH + (k - EE)];
    }
    for (int idx = tid; idx < BT * HH; idx += 128)
        hs[idx / HH][idx % HH] = h_prev[b0 * HH + idx];
    __syncthreads();

    float a0[BT] = {0.f, 0.f};
    float a1[BT] = {0.f, 0.f};
    float a2[BT] = {0.f, 0.f};
    float a3[BT] = {0.f, 0.f};

    #pragma unroll 4
    for (int k = 0; k < KXX; k++) {
        const float* wr = Wk + (size_t)k * FH;
        float w0 = wr[jg], w1 = wr[jg + HH], w2 = wr[jg + 2 * HH], w3 = wr[jg + 3 * HH];
        #pragma unroll
        for (int bb = 0; bb < BT; bb++) {
            float xv = xs[bb][k];
            a0[bb] += w0 * xv; a1[bb] += w1 * xv;
            a2[bb] += w2 * xv; a3[bb] += w3 * xv;
        }
    }
    #pragma unroll 4
    for (int k = 0; k < HH; k++) {
        const float* wr = Uk + (size_t)k * FH;
        float w0 = wr[jg], w1 = wr[jg + HH], w2 = wr[jg + 2 * HH], w3 = wr[jg + 3 * HH];
        #pragma unroll
        for (int bb = 0; bb < BT; bb++) {
            float hv = hs[bb][k];
            a0[bb] += w0 * hv; a1[bb] += w1 * hv;
            a2[bb] += w2 * hv; a3[bb] += w3 * hv;
        }
    }

    const float bi = bias[jg], bf = bias[jg + HH],
                bg = bias[jg + 2 * HH], bo = bias[jg + 3 * HH];
    #pragma unroll
    for (int bb = 0; bb < BT; bb++) {
        int b = b0 + bb;
        float ig = sigm(a0[bb] + bi);
        float fg = sigm(a1[bb] + bf);
        float gg = tanhf(a2[bb] + bg);
        float og = sigm(a3[bb] + bo);
        float c  = fg * c_prev[b * HH + jg] + ig * gg;
        float h  = og * tanhf(c);
        out_c[b * HH + jg] = c;
        out_h[b * HH + jg] = h;
        g_h[b * HH + jg]   = h;
    }
}

// =====================================================================
// Kernel 2: u = h @ W2h   (64x512, K=512).  grid 64, block 512.
// =====================================================================
__global__ void u_kernel(const float* __restrict__ W2h)
{
    __shared__ float hsh[HH];
    const int b = blockIdx.x, j = threadIdx.x;
    hsh[j] = g_h[b * HH + j];
    __syncthreads();
    float acc = 0.f;
    #pragma unroll 8
    for (int k = 0; k < HH; k++)
        acc += hsh[k] * W2h[(size_t)k * HH + j];
    g_u[b * HH + j] = acc;
}

// =====================================================================
// Kernel 3 (dominant): tensor-core 3xTF32 fused scores kernel.
//   scores[b,l] = sum_n tanh((seq@W1e)[b,l,n] + u[b,n]) * beta[n]
// Block: 128m x 64n tile, K=512, n-chunks nc=8, k-tile 16.
// 256 threads = 8 warps (4m x 2n), warp tile 32x32 via m16n8k8 mma.
// smem: exactly 32 KB static.
// =====================================================================
__global__ void __launch_bounds__(256, 2)
scores_tc(const float* __restrict__ seq,
          const float* __restrict__ beta)
{
    __shared__ float2 As[128][18];   // [m][k], (hi,lo), pad to 18
    __shared__ float2 Bs[64][18];    // [n][k], (hi,lo)
    __shared__ float  ush[512];
    __shared__ float  bsh[512];
    __shared__ float  sred[2][128];

    const int b    = blockIdx.y;
    const int l0   = blockIdx.x * 128;
    const int tid  = threadIdx.x;
    const int lane = tid & 31;
    const int wid  = tid >> 5;
    const int wm   = wid >> 1;        // 0..3 (m)
    const int wn   = wid & 1;         // 0..1 (n)
    const int g    = lane >> 2;       // group id (0..7)
    const int tg   = lane & 3;        // thread-in-group

    for (int i = tid; i < 512; i += 256) {
        ush[i] = g_u[b * 512 + i];
        bsh[i] = beta[i];
    }

    const float* seqb = seq + ((size_t)b * LL + l0) * 512;

    // loader mappings
    const int am  = tid >> 1;             // A row (0..127)
    const int akb = (tid & 1) * 8;        // A k-base {0,8}
    const int bk  = tid >> 4;             // B k (0..15)
    const int bn4 = (tid & 15) * 4;       // B n-base (0..60)

    float sacc[2][2] = {{0.f, 0.f}, {0.f, 0.f}};   // [mt][row-half]

    for (int nc = 0; nc < 8; nc++) {
        const int n0 = nc * 64;
        float acc[2][4][4];               // [mt][nt][creg]
        #pragma unroll
        for (int mt = 0; mt < 2; mt++)
            #pragma unroll
            for (int nt = 0; nt < 4; nt++)
                #pragma unroll
                for (int r = 0; r < 4; r++) acc[mt][nt][r] = 0.f;

        for (int kt = 0; kt < 32; kt++) {
            const int k0 = kt * 16;
            __syncthreads();   // prior consumers done
            {
                const float* src = seqb + (size_t)am * 512 + k0 + akb;
                #pragma unroll
                for (int i = 0; i < 8; i++)
                    As[am][akb + i] = split_tf32(src[i]);
            }
            {
                const float2* src = g_W1e2 + (size_t)(k0 + bk) * 512 + n0 + bn4;
                #pragma unroll
                for (int i = 0; i < 4; i++)
                    Bs[bn4 + i][bk] = src[i];
            }
            __syncthreads();

            #pragma unroll
            for (int ks = 0; ks < 2; ks++) {
                const int kk = ks * 8 + tg;
                float2 a[2][4];
                #pragma unroll
                for (int mt = 0; mt < 2; mt++) {
                    const int mr = wm * 32 + mt * 16 + g;
                    a[mt][0] = As[mr][kk];
                    a[mt][1] = As[mr + 8][kk];
                    a[mt][2] = As[mr][kk + 4];
                    a[mt][3] = As[mr + 8][kk + 4];
                }
                float2 bf[4][2];
                #pragma unroll
                for (int nt = 0; nt < 4; nt++) {
                    const int nr = wn * 32 + nt * 8 + g;
                    bf[nt][0] = Bs[nr][kk];
                    bf[nt][1] = Bs[nr][kk + 4];
                }
                #pragma unroll
                for (int mt = 0; mt < 2; mt++)
                    #pragma unroll
                    for (int nt = 0; nt < 4; nt++) {
                        float* c = acc[mt][nt];
                        // hi * hi
                        mma_tf32(c,
                            __float_as_uint(a[mt][0].x), __float_as_uint(a[mt][1].x),
                            __float_as_uint(a[mt][2].x), __float_as_uint(a[mt][3].x),
                            __float_as_uint(bf[nt][0].x), __float_as_uint(bf[nt][1].x));
                        // hi * lo
                        mma_tf32(c,
                            __float_as_uint(a[mt][0].x), __float_as_uint(a[mt][1].x),
                            __float_as_uint(a[mt][2].x), __float_as_uint(a[mt][3].x),
                            __float_as_uint(bf[nt][0].y), __float_as_uint(bf[nt][1].y));
                        // lo * hi
                        mma_tf32(c,
                            __float_as_uint(a[mt][0].y), __float_as_uint(a[mt][1].y),
                            __float_as_uint(a[mt][2].y), __float_as_uint(a[mt][3].y),
                            __float_as_uint(bf[nt][0].x), __float_as_uint(bf[nt][1].x));
                    }
            }
        }

        // epilogue for this n-chunk: tanh(acc + u) * beta, fold into sacc
        #pragma unroll
        for (int mt = 0; mt < 2; mt++)
            #pragma unroll
            for (int nt = 0; nt < 4; nt++) {
                const int nb = n0 + wn * 32 + nt * 8 + 2 * tg;
                const float u0 = ush[nb],     u1 = ush[nb + 1];
                const float e0 = bsh[nb],     e1 = bsh[nb + 1];
                sacc[mt][0] += fast_tanh(acc[mt][nt][0] + u0) * e0
                             + fast_tanh(acc[mt][nt][1] + u1) * e1;
                sacc[mt][1] += fast_tanh(acc[mt][nt][2] + u0) * e0
                             + fast_tanh(acc[mt][nt][3] + u1) * e1;
            }
    }

    // reduce across the 4 lanes (tg) sharing each row, then across warp_n
    #pragma unroll
    for (int mt = 0; mt < 2; mt++)
        #pragma unroll
        for (int r = 0; r < 2; r++) {
            float v = sacc[mt][r];
            v += __shfl_xor_sync(0xFFFFFFFFu, v, 1);
            v += __shfl_xor_sync(0xFFFFFFFFu, v, 2);
            if (tg == 0)
                sred[wn][wm * 32 + mt * 16 + r * 8 + g] = v;
        }
    __syncthreads();
    if (tid < 128)
        g_alpha[b * LL + l0 + tid] = sred[0][tid] + sred[1][tid];
}

// =====================================================================
// Kernel 4: softmax over L per batch (in place in g_alpha).
// =====================================================================
__global__ void softmax_kernel()
{
    __shared__ float red[256];
    const int b = blockIdx.x, tid = threadIdx.x;
    float v[4];
    float mx = -1e30f;
    #pragma unroll
    for (int i = 0; i < 4; i++) {
        v[i] = g_alpha[b * LL + i * 256 + tid];
        mx = fmaxf(mx, v[i]);
    }
    red[tid] = mx; __syncthreads();
    for (int s = 128; s > 0; s >>= 1) {
        if (tid < s) red[tid] = fmaxf(red[tid], red[tid + s]);
        __syncthreads();
    }
    mx = red[0]; __syncthreads();

    float sum = 0.f;
    #pragma unroll
    for (int i = 0; i < 4; i++) {
        v[i] = __expf(v[i] - mx);
        sum += v[i];
    }
    red[tid] = sum; __syncthreads();
    for (int s = 128; s > 0; s >>= 1) {
        if (tid < s) red[tid] += red[tid + s];
        __syncthreads();
    }
    float inv = __fdividef(1.0f, red[0]);
    #pragma unroll
    for (int i = 0; i < 4; i++)
        g_alpha[b * LL + i * 256 + tid] = v[i] * inv;
}

// =====================================================================
// Kernel 5: ctx[b,d] = sum_l alpha[b,l] * seq[b,l,d].  grid (64,2) x 256.
// =====================================================================
__global__ void ctx_kernel(const float* __restrict__ seq)
{
    __shared__ float al[LL];
    const int b = blockIdx.x;
    const int d = blockIdx.y * 256 + threadIdx.x;
    for (int i = threadIdx.x; i < LL; i += 256)
        al[i] = g_alpha[b * LL + i];
    __syncthreads();

    const float* sp = seq + (size_t)b * LL * 512 + d;
    float acc0 = 0.f, acc1 = 0.f, acc2 = 0.f, acc3 = 0.f;
    #pragma unroll 4
    for (int l = 0; l < LL; l += 4) {
        acc0 += al[l]     * sp[(size_t)l * 512];
        acc1 += al[l + 1] * sp[(size_t)(l + 1) * 512];
        acc2 += al[l + 2] * sp[(size_t)(l + 2) * 512];
        acc3 += al[l + 3] * sp[(size_t)(l + 3) * 512];
    }
    g_ctx[b * DEE + d] = (acc0 + acc1) + (acc2 + acc3);
}

// =====================================================================
// Kernel 6: new_o = tanh([h, ctx] @ W3o).  grid 32, block 512, BT=2.
// =====================================================================
__global__ void newo_kernel(const float* __restrict__ W3o,
                            float* __restrict__ out_newo)
{
    const int BT = 2;
    __shared__ float hc[BT][1024];
    const int b0 = blockIdx.x * BT;
    const int j  = threadIdx.x;
    for (int idx = j; idx < BT * 1024; idx += 512) {
        int bb = idx / 1024, k = idx % 1024;
        hc[bb][k] = (k < 512) ? g_h[(b0 + bb) * 512 + k]
                              : g_ctx[(b0 + bb) * 512 + (k - 512)];
    }
    __syncthreads();
    float a[BT] = {0.f, 0.f};
    #pragma unroll 4
    for (int k = 0; k < 1024; k++) {
        float w = W3o[(size_t)k * 512 + j];
        #pragma unroll
        for (int bb = 0; bb < BT; bb++) a[bb] += hc[bb][k] * w;
    }
    #pragma unroll
    for (int bb = 0; bb < BT; bb++) {
        float t = tanhf(a[bb]);
        g_newo[(b0 + bb) * 512 + j]    = t;
        out_newo[(b0 + bb) * 512 + j]  = t;
    }
}

// =====================================================================
// Kernel 7: logits = new_o @ W4.  grid 32, block 512 (500 active), BT=2.
// =====================================================================
__global__ void logits_kernel(const float* __restrict__ W4,
                              float* __restrict__ out_logits)
{
    const int BT = 2;
    __shared__ float no[BT][512];
    const int b0 = blockIdx.x * BT;
    const int j  = threadIdx.x;
    for (int idx = j; idx < BT * 512; idx += 512)
        no[idx / 512][idx % 512] = g_newo[b0 * 512 + idx];
    __syncthreads();
    if (j < VV) {
        float a[BT] = {0.f, 0.f};
        #pragma unroll 4
        for (int k = 0; k < 512; k++) {
            float w = W4[(size_t)k * VV + j];
            #pragma unroll
            for (int bb = 0; bb < BT; bb++) a[bb] += no[bb][k] * w;
        }
        #pragma unroll
        for (int bb = 0; bb < BT; bb++)
            out_logits[(b0 + bb) * VV + j] = a[bb];
    }
}

// =====================================================================
extern "C" void kernel_launch(void* const* d_in, const int* in_sizes, int n_in,
                              void* d_out, int out_size)
{
    (void)in_sizes; (void)n_in; (void)out_size;
    const float* inputs = (const float*)d_in[0];
    const float* seq    = (const float*)d_in[1];
    const float* h_prev = (const float*)d_in[2];
    const float* c_prev = (const float*)d_in[3];
    const float* o_prev = (const float*)d_in[4];
    const float* Wk     = (const float*)d_in[5];
    const float* Uk     = (const float*)d_in[6];
    const float* bias   = (const float*)d_in[7];
    const float* W1e    = (const float*)d_in[8];
    const float* W2h    = (const float*)d_in[9];
    const float* beta   = (const float*)d_in[10];
    const float* W3o    = (const float*)d_in[11];
    const float* W4     = (const float*)d_in[12];

    float* out        = (float*)d_out;
    float* out_logits = out;                         // 64*500
    float* out_h      = out + BB * VV;               // 64*512
    float* out_c      = out_h + BB * HH;             // 64*512
    float* out_newo   = out_c + BB * HH;             // 64*512

    split_w1e_kernel<<<1024, 256>>>(W1e);
    lstm_kernel  <<<dim3(4, 32), 128>>>(inputs, o_prev, h_prev, c_prev,
                                        Wk, Uk, bias, out_h, out_c);
    u_kernel     <<<64, 512>>>(W2h);
    scores_tc    <<<dim3(8, 64), 256>>>(seq, beta);
    softmax_kernel<<<64, 256>>>();
    ctx_kernel   <<<dim3(64, 2), 256>>>(seq);
    newo_kernel  <<<32, 512>>>(W3o, out_newo);
    logits_kernel<<<32, 512>>>(W4, out_logits);
}